// round 13
// baseline (speedup 1.0000x reference)
#include <cuda_runtime.h>
#include <math_constants.h>

// ---------------------------------------------------------------------------
// SC_Att_Bridge: 5-level spatial attention (CBAM-style), fp32.
// Phase-pipelined across tensors (4 launches, mixed-phase grids):
//   K1: reduce(t1)
//   K2: reduce(t2..t5) + conv(t1)        (conv t1 dep: K1)
//   K3: conv(t2..t5)  + gate(t1)         (deps: K2)
//   K4: gate(t2..t5)                     (dep: K3)
// R12 bug fixed: s_att must be 16B-aligned (mixed kernels place it after
// conv's 9640B of shared -> misaligned float4 access without __align__).
// ---------------------------------------------------------------------------

#define NTOT_PIX 698368   // sum over tensors of N*H*W (N=8)

__device__ float g_avg[NTOT_PIX];
__device__ float g_max[NTOT_PIX];
__device__ float g_att[NTOT_PIX];

// shapes: (8,64,256,256)(8,128,128,128)(8,256,64,64)(8,512,32,32)(8,512,16,16)
__constant__ int c_C[5]       = {64, 128, 256, 512, 512};
__constant__ int c_HW[5]      = {65536, 16384, 4096, 1024, 256};
__constant__ int c_lgHW[5]    = {16, 14, 12, 10, 8};
__constant__ int c_W[5]       = {256, 128, 64, 32, 16};
__constant__ int c_poff[5]    = {0, 524288, 655360, 688128, 696320};          // pixel offsets
__constant__ int c_eoff[5]    = {0, 33554432, 50331648, 58720256, 62914560};  // element offsets
__constant__ int c_convcum[5] = {0, 2048, 2560, 2688, 2720};   // conv blocks
__constant__ int c_tpn[5]     = {256, 64, 16, 4, 1};           // 16x16 tiles per image
__constant__ int c_tilesX[5]  = {16, 8, 4, 2, 1};

// reduce tiling (R11): P = 512,256,128,64,32 ; nsub = 2,4,8,16,32 ;
// blocks/image = 128,64,32,16,8 -> 1024,512,256,128,64 = 1984 total.
// Order: t5,t4,t3,t2 in [0,960), t1 in [960,1984).
__constant__ int c_rstart[5]  = {960, 448, 192, 64, 0};
__constant__ int c_lgP[5]     = {9, 8, 7, 6, 5};
__constant__ int c_lgns[5]    = {1, 2, 3, 4, 5};
__constant__ int c_lgbpi[5]   = {7, 6, 5, 4, 3};

// gate tiling: 8192 elements/block; t1 in [0,4096), t2..t5 in [4096,7808)
__constant__ int c_gcum[5]    = {0, 4096, 6144, 7168, 7680};
__constant__ int c_lgpnb[5]   = {9, 8, 7, 6, 4};
__constant__ int c_lgnhw[5]   = {6, 4, 2, 0, 0};
__constant__ int c_lgnch[5]   = {3, 3, 3, 3, 5};
__constant__ int c_lgchunk[5] = {10, 10, 10, 10, 8};

// ---------------------------------------------------------------------------
// reduce body: b = reduce-block id in [0,1984)
// ---------------------------------------------------------------------------
__device__ __forceinline__ void do_reduce(
    int b,
    const float* __restrict__ t0, const float* __restrict__ t1,
    const float* __restrict__ t2, const float* __restrict__ t3,
    const float* __restrict__ t4)
{
    __shared__ float4 sh_s[256];
    __shared__ float4 sh_m[256];

    int i;
    if      (b < 64)  i = 4;
    else if (b < 192) i = 3;
    else if (b < 448) i = 2;
    else if (b < 960) i = 1;
    else              i = 0;

    const float* srcs[5] = {t0, t1, t2, t3, t4};
    const float* __restrict__ src = srcs[i];

    const int tid   = threadIdx.x;
    const int r     = b - c_rstart[i];
    const int lgP   = c_lgP[i];
    const int lgns  = c_lgns[i];
    const int lgbpi = c_lgbpi[i];
    const int nsub  = 1 << lgns;
    const int Tpx   = 256 >> lgns;

    const int n     = r >> lgbpi;
    const int chunk = r & ((1 << lgbpi) - 1);
    const int hw0   = chunk << lgP;

    const int HW = c_HW[i];
    const int C  = c_C[i];
    const int sub = tid >> (8 - lgns);
    const int pxt = tid & (Tpx - 1);

    const float4* __restrict__ p = reinterpret_cast<const float4*>(
        src + ((size_t)(n * C + sub)) * HW + hw0 + (pxt << 2));
    const size_t step4 = ((size_t)HW << lgns) >> 2;   // nsub*HW floats / 4

    float4 s = make_float4(0.f, 0.f, 0.f, 0.f);
    float4 m = make_float4(-CUDART_INF_F, -CUDART_INF_F, -CUDART_INF_F, -CUDART_INF_F);

    const int iters = C >> (lgns + 2);                // 8,8,8,8,4
    for (int it = 0; it < iters; it++) {
        float4 v0 = __ldg(p);
        float4 v1 = __ldg(p + step4);
        float4 v2 = __ldg(p + 2 * step4);
        float4 v3 = __ldg(p + 3 * step4);
        p += 4 * step4;
        s.x += v0.x + v1.x; s.y += v0.y + v1.y; s.z += v0.z + v1.z; s.w += v0.w + v1.w;
        s.x += v2.x + v3.x; s.y += v2.y + v3.y; s.z += v2.z + v3.z; s.w += v2.w + v3.w;
        m.x = fmaxf(fmaxf(m.x, v0.x), fmaxf(v1.x, fmaxf(v2.x, v3.x)));
        m.y = fmaxf(fmaxf(m.y, v0.y), fmaxf(v1.y, fmaxf(v2.y, v3.y)));
        m.z = fmaxf(fmaxf(m.z, v0.z), fmaxf(v1.z, fmaxf(v2.z, v3.z)));
        m.w = fmaxf(fmaxf(m.w, v0.w), fmaxf(v1.w, fmaxf(v2.w, v3.w)));
    }

    sh_s[tid] = s;
    sh_m[tid] = m;
    __syncthreads();
    if (tid < Tpx) {
        for (int k = 1; k < nsub; k++) {
            float4 s2 = sh_s[tid + k * Tpx];
            float4 m2 = sh_m[tid + k * Tpx];
            s.x += s2.x; s.y += s2.y; s.z += s2.z; s.w += s2.w;
            m.x = fmaxf(m.x, m2.x); m.y = fmaxf(m.y, m2.y);
            m.z = fmaxf(m.z, m2.z); m.w = fmaxf(m.w, m2.w);
        }
        const float inv = 1.0f / (float)C;
        s.x *= inv; s.y *= inv; s.z *= inv; s.w *= inv;
        const int ppix = c_poff[i] + (n << c_lgHW[i]) + hw0 + (pxt << 2);
        const int q4 = ppix >> 2;
        reinterpret_cast<float4*>(g_avg)[q4] = s;
        reinterpret_cast<float4*>(g_max)[q4] = m;
    }
}

// ---------------------------------------------------------------------------
// conv body: b = conv-block id in [0,2728). t1 = [0,2048), t2..5 = [2048,2728)
// ---------------------------------------------------------------------------
__device__ __forceinline__ void do_conv(
    int b, const float* __restrict__ cw, const float* __restrict__ cb)
{
    __shared__ float s_av[34 * 34];
    __shared__ float s_mx[34 * 34];
    __shared__ float s_w[98];

    int i = 0;
    if (b >= 2048) i = 1;
    if (b >= 2560) i = 2;
    if (b >= 2688) i = 3;
    if (b >= 2720) i = 4;

    const int r      = b - c_convcum[i];
    const int tpn    = c_tpn[i];
    const int n      = r / tpn;
    const int tl     = r - n * tpn;
    const int tilesX = c_tilesX[i];
    const int ty0    = (tl / tilesX) << 4;
    const int tx0    = (tl % tilesX) << 4;
    const int Wd     = c_W[i];
    const int po     = c_poff[i] + (n << c_lgHW[i]);

    const int tid = threadIdx.x;
    if (tid < 98) s_w[tid] = cw[tid];

    for (int idx = tid; idx < 34 * 34; idx += 256) {
        int yy = idx / 34;
        int xx = idx - yy * 34;
        int h  = ty0 + yy - 9;
        int w  = tx0 + xx - 9;
        float a = 0.0f, m = 0.0f;
        if ((unsigned)h < (unsigned)Wd && (unsigned)w < (unsigned)Wd) { // H==W
            int q = po + h * Wd + w;
            a = g_avg[q];
            m = g_max[q];
        }
        s_av[idx] = a;
        s_mx[idx] = m;
    }
    __syncthreads();

    const int ty = tid >> 4;
    const int tx = tid & 15;

    float acc = cb[0];
#pragma unroll
    for (int kh = 0; kh < 7; kh++) {
#pragma unroll
        for (int kw = 0; kw < 7; kw++) {
            int s = (ty + kh * 3) * 34 + (tx + kw * 3);
            acc = fmaf(s_av[s], s_w[kh * 7 + kw],      acc);
            acc = fmaf(s_mx[s], s_w[49 + kh * 7 + kw], acc);
        }
    }
    float att = 1.0f / (1.0f + expf(-acc));
    g_att[po + (ty0 + ty) * Wd + (tx0 + tx)] = att;
}

// ---------------------------------------------------------------------------
// gate body: b = gate-block id in [0,7808). t1 = [0,4096), rest after.
// s_att MUST be 16B-aligned: in mixed kernels it is placed after conv's
// shared arrays (9640 bytes) and float4 access traps without __align__(16).
// ---------------------------------------------------------------------------
__device__ __forceinline__ void do_gate(
    int b,
    const float* __restrict__ t0, const float* __restrict__ t1,
    const float* __restrict__ t2, const float* __restrict__ t3,
    const float* __restrict__ t4, float* __restrict__ out)
{
    __shared__ __align__(16) float s_att[1024];

    int i = 0;
    if (b >= 4096) i = 1;
    if (b >= 6144) i = 2;
    if (b >= 7168) i = 3;
    if (b >= 7680) i = 4;

    const float* srcs[5] = {t0, t1, t2, t3, t4};
    const float* __restrict__ src = srcs[i];

    const int tid     = threadIdx.x;
    const int r       = b - c_gcum[i];
    const int lgpnb   = c_lgpnb[i];
    const int lgnhw   = c_lgnhw[i];
    const int lgnch   = c_lgnch[i];
    const int lgchunk = c_lgchunk[i];
    const int lgHW    = c_lgHW[i];

    const int n      = r >> lgpnb;
    const int rem    = r & ((1 << lgpnb) - 1);
    const int cchunk = rem >> lgnhw;
    const int hwc    = rem & ((1 << lgnhw) - 1);
    const int c0     = cchunk << lgnch;
    const int hw0    = hwc << lgchunk;
    const int chunkpx = 1 << lgchunk;

    const int ebase   = ((n * c_C[i] + c0) << lgHW) + hw0;
    const int attbase = c_poff[i] + (n << lgHW) + hw0;

    if (tid < (chunkpx >> 2)) {
        reinterpret_cast<float4*>(s_att)[tid] =
            *reinterpret_cast<const float4*>(&g_att[attbase + (tid << 2)]);
    }
    __syncthreads();

    const int chunkm1 = chunkpx - 1;

    float4 v[8];
#pragma unroll
    for (int j = 0; j < 8; j++) {
        int f  = ((j << 8) + tid) << 2;
        int ch = f >> lgchunk;
        int px = f & chunkm1;
        v[j] = *reinterpret_cast<const float4*>(&src[ebase + (ch << lgHW) + px]);
    }
    const int eoff = c_eoff[i];
#pragma unroll
    for (int j = 0; j < 8; j++) {
        int f  = ((j << 8) + tid) << 2;
        int ch = f >> lgchunk;
        int px = f & chunkm1;
        float4 a = *reinterpret_cast<const float4*>(&s_att[px]);
        float4 o;
        o.x = fmaf(v[j].x, a.x, v[j].x);
        o.y = fmaf(v[j].y, a.y, v[j].y);
        o.z = fmaf(v[j].z, a.z, v[j].z);
        o.w = fmaf(v[j].w, a.w, v[j].w);
        *reinterpret_cast<float4*>(&out[eoff + ebase + (ch << lgHW) + px]) = o;
    }
}

// ---------------------------------------------------------------------------
// K1: reduce(t1) = reduce blocks [960,1984)
__global__ __launch_bounds__(256, 4) void k1_reduce_t1(
    const float* __restrict__ t0, const float* __restrict__ t1,
    const float* __restrict__ t2, const float* __restrict__ t3,
    const float* __restrict__ t4)
{
    do_reduce(blockIdx.x + 960, t0, t1, t2, t3, t4);
}

// K2: reduce(t2..t5) [0,960) + conv(t1) [0,2048). Grid = 3008.
__global__ __launch_bounds__(256, 4) void k2_red_conv(
    const float* __restrict__ t0, const float* __restrict__ t1,
    const float* __restrict__ t2, const float* __restrict__ t3,
    const float* __restrict__ t4,
    const float* __restrict__ cw, const float* __restrict__ cb)
{
    const int b = blockIdx.x;
    if (b < 960) do_reduce(b, t0, t1, t2, t3, t4);
    else         do_conv(b - 960, cw, cb);
}

// K3: conv(t2..t5) [2048,2728) + gate(t1) [0,4096). Grid = 4776.
__global__ __launch_bounds__(256, 4) void k3_conv_gate(
    const float* __restrict__ t0, const float* __restrict__ t1,
    const float* __restrict__ t2, const float* __restrict__ t3,
    const float* __restrict__ t4,
    const float* __restrict__ cw, const float* __restrict__ cb,
    float* __restrict__ out)
{
    const int b = blockIdx.x;
    if (b < 680) do_conv(b + 2048, cw, cb);
    else         do_gate(b - 680, t0, t1, t2, t3, t4, out);
}

// K4: gate(t2..t5) [4096,7808). Grid = 3712.
__global__ __launch_bounds__(256, 4) void k4_gate_rest(
    const float* __restrict__ t0, const float* __restrict__ t1,
    const float* __restrict__ t2, const float* __restrict__ t3,
    const float* __restrict__ t4, float* __restrict__ out)
{
    do_gate(blockIdx.x + 4096, t0, t1, t2, t3, t4, out);
}

// ---------------------------------------------------------------------------
extern "C" void kernel_launch(void* const* d_in, const int* in_sizes, int n_in,
                              void* d_out, int out_size)
{
    const float* t0 = (const float*)d_in[0];
    const float* t1 = (const float*)d_in[1];
    const float* t2 = (const float*)d_in[2];
    const float* t3 = (const float*)d_in[3];
    const float* t4 = (const float*)d_in[4];
    const float* cw = (const float*)d_in[5];
    const float* cb = (const float*)d_in[6];
    float* out = (float*)d_out;

    k1_reduce_t1<<<1024, 256>>>(t0, t1, t2, t3, t4);
    k2_red_conv<<<3008, 256>>>(t0, t1, t2, t3, t4, cw, cb);
    k3_conv_gate<<<4776, 256>>>(t0, t1, t2, t3, t4, cw, cb, out);
    k4_gate_rest<<<3712, 256>>>(t0, t1, t2, t3, t4, out);
}

// round 14
// speedup vs baseline: 1.0002x; 1.0002x over previous
#include <cuda_runtime.h>
#include <math_constants.h>

// ---------------------------------------------------------------------------
// SC_Att_Bridge: 5-level spatial attention (CBAM-style), fp32.
// Phase-pipelined across tensors (4 launches, mixed-phase grids):
//   K1: reduce(t1)                         [launch_bounds(256,4): reduce regs]
//   K2: reduce(t2..t5) + conv(t1)          [launch_bounds(256,4)]
//   K3: conv(t2..t5)  + gate(t1)           [launch_bounds(256): gate occupancy]
//   K4: gate(t2..t5)                       [launch_bounds(256)]
// R13 bug fixed: (256,4) on gate legs capped regs at 64 -> occ 42%, DRAM 64%.
// ---------------------------------------------------------------------------

#define NTOT_PIX 698368   // sum over tensors of N*H*W (N=8)

__device__ float g_avg[NTOT_PIX];
__device__ float g_max[NTOT_PIX];
__device__ float g_att[NTOT_PIX];

// shapes: (8,64,256,256)(8,128,128,128)(8,256,64,64)(8,512,32,32)(8,512,16,16)
__constant__ int c_C[5]       = {64, 128, 256, 512, 512};
__constant__ int c_HW[5]      = {65536, 16384, 4096, 1024, 256};
__constant__ int c_lgHW[5]    = {16, 14, 12, 10, 8};
__constant__ int c_W[5]       = {256, 128, 64, 32, 16};
__constant__ int c_poff[5]    = {0, 524288, 655360, 688128, 696320};          // pixel offsets
__constant__ int c_eoff[5]    = {0, 33554432, 50331648, 58720256, 62914560};  // element offsets
__constant__ int c_convcum[5] = {0, 2048, 2560, 2688, 2720};   // conv blocks
__constant__ int c_tpn[5]     = {256, 64, 16, 4, 1};           // 16x16 tiles per image
__constant__ int c_tilesX[5]  = {16, 8, 4, 2, 1};

// reduce tiling: P = 512,256,128,64,32 ; nsub = 2,4,8,16,32 ;
// blocks/image = 128,64,32,16,8 -> 1024,512,256,128,64 = 1984 total.
// Order: t5,t4,t3,t2 in [0,960), t1 in [960,1984).
__constant__ int c_rstart[5]  = {960, 448, 192, 64, 0};
__constant__ int c_lgP[5]     = {9, 8, 7, 6, 5};
__constant__ int c_lgns[5]    = {1, 2, 3, 4, 5};
__constant__ int c_lgbpi[5]   = {7, 6, 5, 4, 3};

// gate tiling: 8192 elements/block; t1 in [0,4096), t2..t5 in [4096,7808)
__constant__ int c_gcum[5]    = {0, 4096, 6144, 7168, 7680};
__constant__ int c_lgpnb[5]   = {9, 8, 7, 6, 4};
__constant__ int c_lgnhw[5]   = {6, 4, 2, 0, 0};
__constant__ int c_lgnch[5]   = {3, 3, 3, 3, 5};
__constant__ int c_lgchunk[5] = {10, 10, 10, 10, 8};

// ---------------------------------------------------------------------------
// reduce body: b = reduce-block id in [0,1984)
// ---------------------------------------------------------------------------
__device__ __forceinline__ void do_reduce(
    int b,
    const float* __restrict__ t0, const float* __restrict__ t1,
    const float* __restrict__ t2, const float* __restrict__ t3,
    const float* __restrict__ t4)
{
    __shared__ float4 sh_s[256];
    __shared__ float4 sh_m[256];

    int i;
    if      (b < 64)  i = 4;
    else if (b < 192) i = 3;
    else if (b < 448) i = 2;
    else if (b < 960) i = 1;
    else              i = 0;

    const float* srcs[5] = {t0, t1, t2, t3, t4};
    const float* __restrict__ src = srcs[i];

    const int tid   = threadIdx.x;
    const int r     = b - c_rstart[i];
    const int lgP   = c_lgP[i];
    const int lgns  = c_lgns[i];
    const int lgbpi = c_lgbpi[i];
    const int nsub  = 1 << lgns;
    const int Tpx   = 256 >> lgns;

    const int n     = r >> lgbpi;
    const int chunk = r & ((1 << lgbpi) - 1);
    const int hw0   = chunk << lgP;

    const int HW = c_HW[i];
    const int C  = c_C[i];
    const int sub = tid >> (8 - lgns);
    const int pxt = tid & (Tpx - 1);

    const float4* __restrict__ p = reinterpret_cast<const float4*>(
        src + ((size_t)(n * C + sub)) * HW + hw0 + (pxt << 2));
    const size_t step4 = ((size_t)HW << lgns) >> 2;   // nsub*HW floats / 4

    float4 s = make_float4(0.f, 0.f, 0.f, 0.f);
    float4 m = make_float4(-CUDART_INF_F, -CUDART_INF_F, -CUDART_INF_F, -CUDART_INF_F);

    const int iters = C >> (lgns + 2);                // 8,8,8,8,4
    for (int it = 0; it < iters; it++) {
        float4 v0 = __ldg(p);
        float4 v1 = __ldg(p + step4);
        float4 v2 = __ldg(p + 2 * step4);
        float4 v3 = __ldg(p + 3 * step4);
        p += 4 * step4;
        s.x += v0.x + v1.x; s.y += v0.y + v1.y; s.z += v0.z + v1.z; s.w += v0.w + v1.w;
        s.x += v2.x + v3.x; s.y += v2.y + v3.y; s.z += v2.z + v3.z; s.w += v2.w + v3.w;
        m.x = fmaxf(fmaxf(m.x, v0.x), fmaxf(v1.x, fmaxf(v2.x, v3.x)));
        m.y = fmaxf(fmaxf(m.y, v0.y), fmaxf(v1.y, fmaxf(v2.y, v3.y)));
        m.z = fmaxf(fmaxf(m.z, v0.z), fmaxf(v1.z, fmaxf(v2.z, v3.z)));
        m.w = fmaxf(fmaxf(m.w, v0.w), fmaxf(v1.w, fmaxf(v2.w, v3.w)));
    }

    sh_s[tid] = s;
    sh_m[tid] = m;
    __syncthreads();
    if (tid < Tpx) {
        for (int k = 1; k < nsub; k++) {
            float4 s2 = sh_s[tid + k * Tpx];
            float4 m2 = sh_m[tid + k * Tpx];
            s.x += s2.x; s.y += s2.y; s.z += s2.z; s.w += s2.w;
            m.x = fmaxf(m.x, m2.x); m.y = fmaxf(m.y, m2.y);
            m.z = fmaxf(m.z, m2.z); m.w = fmaxf(m.w, m2.w);
        }
        const float inv = 1.0f / (float)C;
        s.x *= inv; s.y *= inv; s.z *= inv; s.w *= inv;
        const int ppix = c_poff[i] + (n << c_lgHW[i]) + hw0 + (pxt << 2);
        const int q4 = ppix >> 2;
        reinterpret_cast<float4*>(g_avg)[q4] = s;
        reinterpret_cast<float4*>(g_max)[q4] = m;
    }
}

// ---------------------------------------------------------------------------
// conv body: b = conv-block id in [0,2728). t1 = [0,2048), t2..5 = [2048,2728)
// ---------------------------------------------------------------------------
__device__ __forceinline__ void do_conv(
    int b, const float* __restrict__ cw, const float* __restrict__ cb)
{
    __shared__ float s_av[34 * 34];
    __shared__ float s_mx[34 * 34];
    __shared__ float s_w[98];

    int i = 0;
    if (b >= 2048) i = 1;
    if (b >= 2560) i = 2;
    if (b >= 2688) i = 3;
    if (b >= 2720) i = 4;

    const int r      = b - c_convcum[i];
    const int tpn    = c_tpn[i];
    const int n      = r / tpn;
    const int tl     = r - n * tpn;
    const int tilesX = c_tilesX[i];
    const int ty0    = (tl / tilesX) << 4;
    const int tx0    = (tl % tilesX) << 4;
    const int Wd     = c_W[i];
    const int po     = c_poff[i] + (n << c_lgHW[i]);

    const int tid = threadIdx.x;
    if (tid < 98) s_w[tid] = cw[tid];

    for (int idx = tid; idx < 34 * 34; idx += 256) {
        int yy = idx / 34;
        int xx = idx - yy * 34;
        int h  = ty0 + yy - 9;
        int w  = tx0 + xx - 9;
        float a = 0.0f, m = 0.0f;
        if ((unsigned)h < (unsigned)Wd && (unsigned)w < (unsigned)Wd) { // H==W
            int q = po + h * Wd + w;
            a = g_avg[q];
            m = g_max[q];
        }
        s_av[idx] = a;
        s_mx[idx] = m;
    }
    __syncthreads();

    const int ty = tid >> 4;
    const int tx = tid & 15;

    float acc = cb[0];
#pragma unroll
    for (int kh = 0; kh < 7; kh++) {
#pragma unroll
        for (int kw = 0; kw < 7; kw++) {
            int s = (ty + kh * 3) * 34 + (tx + kw * 3);
            acc = fmaf(s_av[s], s_w[kh * 7 + kw],      acc);
            acc = fmaf(s_mx[s], s_w[49 + kh * 7 + kw], acc);
        }
    }
    float att = 1.0f / (1.0f + expf(-acc));
    g_att[po + (ty0 + ty) * Wd + (tx0 + tx)] = att;
}

// ---------------------------------------------------------------------------
// gate body: b = gate-block id in [0,7808). t1 = [0,4096), rest after.
// s_att 16B-aligned (required when placed after conv's shared arrays).
// ---------------------------------------------------------------------------
__device__ __forceinline__ void do_gate(
    int b,
    const float* __restrict__ t0, const float* __restrict__ t1,
    const float* __restrict__ t2, const float* __restrict__ t3,
    const float* __restrict__ t4, float* __restrict__ out)
{
    __shared__ __align__(16) float s_att[1024];

    int i = 0;
    if (b >= 4096) i = 1;
    if (b >= 6144) i = 2;
    if (b >= 7168) i = 3;
    if (b >= 7680) i = 4;

    const float* srcs[5] = {t0, t1, t2, t3, t4};
    const float* __restrict__ src = srcs[i];

    const int tid     = threadIdx.x;
    const int r       = b - c_gcum[i];
    const int lgpnb   = c_lgpnb[i];
    const int lgnhw   = c_lgnhw[i];
    const int lgnch   = c_lgnch[i];
    const int lgchunk = c_lgchunk[i];
    const int lgHW    = c_lgHW[i];

    const int n      = r >> lgpnb;
    const int rem    = r & ((1 << lgpnb) - 1);
    const int cchunk = rem >> lgnhw;
    const int hwc    = rem & ((1 << lgnhw) - 1);
    const int c0     = cchunk << lgnch;
    const int hw0    = hwc << lgchunk;
    const int chunkpx = 1 << lgchunk;

    const int ebase   = ((n * c_C[i] + c0) << lgHW) + hw0;
    const int attbase = c_poff[i] + (n << lgHW) + hw0;

    if (tid < (chunkpx >> 2)) {
        reinterpret_cast<float4*>(s_att)[tid] =
            *reinterpret_cast<const float4*>(&g_att[attbase + (tid << 2)]);
    }
    __syncthreads();

    const int chunkm1 = chunkpx - 1;

    float4 v[8];
#pragma unroll
    for (int j = 0; j < 8; j++) {
        int f  = ((j << 8) + tid) << 2;
        int ch = f >> lgchunk;
        int px = f & chunkm1;
        v[j] = *reinterpret_cast<const float4*>(&src[ebase + (ch << lgHW) + px]);
    }
    const int eoff = c_eoff[i];
#pragma unroll
    for (int j = 0; j < 8; j++) {
        int f  = ((j << 8) + tid) << 2;
        int ch = f >> lgchunk;
        int px = f & chunkm1;
        float4 a = *reinterpret_cast<const float4*>(&s_att[px]);
        float4 o;
        o.x = fmaf(v[j].x, a.x, v[j].x);
        o.y = fmaf(v[j].y, a.y, v[j].y);
        o.z = fmaf(v[j].z, a.z, v[j].z);
        o.w = fmaf(v[j].w, a.w, v[j].w);
        *reinterpret_cast<float4*>(&out[eoff + ebase + (ch << lgHW) + px]) = o;
    }
}

// ---------------------------------------------------------------------------
// K1: reduce(t1) = reduce blocks [960,1984). Reduce bounds.
__global__ __launch_bounds__(256, 4) void k1_reduce_t1(
    const float* __restrict__ t0, const float* __restrict__ t1,
    const float* __restrict__ t2, const float* __restrict__ t3,
    const float* __restrict__ t4)
{
    do_reduce(blockIdx.x + 960, t0, t1, t2, t3, t4);
}

// K2: reduce(t2..t5) [0,960) + conv(t1) [0,2048). Grid = 3008. Reduce bounds.
__global__ __launch_bounds__(256, 4) void k2_red_conv(
    const float* __restrict__ t0, const float* __restrict__ t1,
    const float* __restrict__ t2, const float* __restrict__ t3,
    const float* __restrict__ t4,
    const float* __restrict__ cw, const float* __restrict__ cb)
{
    const int b = blockIdx.x;
    if (b < 960) do_reduce(b, t0, t1, t2, t3, t4);
    else         do_conv(b - 960, cw, cb);
}

// K3: conv(t2..t5) [2048,2728) + gate(t1) [0,4096). Grid = 4776. Gate bounds.
__global__ __launch_bounds__(256) void k3_conv_gate(
    const float* __restrict__ t0, const float* __restrict__ t1,
    const float* __restrict__ t2, const float* __restrict__ t3,
    const float* __restrict__ t4,
    const float* __restrict__ cw, const float* __restrict__ cb,
    float* __restrict__ out)
{
    const int b = blockIdx.x;
    if (b < 680) do_conv(b + 2048, cw, cb);
    else         do_gate(b - 680, t0, t1, t2, t3, t4, out);
}

// K4: gate(t2..t5) [4096,7808). Grid = 3712. Gate bounds.
__global__ __launch_bounds__(256) void k4_gate_rest(
    const float* __restrict__ t0, const float* __restrict__ t1,
    const float* __restrict__ t2, const float* __restrict__ t3,
    const float* __restrict__ t4, float* __restrict__ out)
{
    do_gate(blockIdx.x + 4096, t0, t1, t2, t3, t4, out);
}

// ---------------------------------------------------------------------------
extern "C" void kernel_launch(void* const* d_in, const int* in_sizes, int n_in,
                              void* d_out, int out_size)
{
    const float* t0 = (const float*)d_in[0];
    const float* t1 = (const float*)d_in[1];
    const float* t2 = (const float*)d_in[2];
    const float* t3 = (const float*)d_in[3];
    const float* t4 = (const float*)d_in[4];
    const float* cw = (const float*)d_in[5];
    const float* cb = (const float*)d_in[6];
    float* out = (float*)d_out;

    k1_reduce_t1<<<1024, 256>>>(t0, t1, t2, t3, t4);
    k2_red_conv<<<3008, 256>>>(t0, t1, t2, t3, t4, cw, cb);
    k3_conv_gate<<<4776, 256>>>(t0, t1, t2, t3, t4, cw, cb, out);
    k4_gate_rest<<<3712, 256>>>(t0, t1, t2, t3, t4, out);
}

// round 15
// speedup vs baseline: 1.0655x; 1.0652x over previous
#include <cuda_runtime.h>
#include <math_constants.h>

// ---------------------------------------------------------------------------
// SC_Att_Bridge: 5-level spatial attention (CBAM-style), fp32.
// 3-kernel structure (best measured: R10/R11 = 147.8us) + streaming cache
// hints: single-use traffic (reduce reads, gate src reads, out writes) uses
// __ldcs/__stcs so L2 keeps the reused avg/max/att maps instead.
// ---------------------------------------------------------------------------

#define NTOT_PIX 698368   // sum over tensors of N*H*W (N=8)

__device__ float g_avg[NTOT_PIX];
__device__ float g_max[NTOT_PIX];
__device__ float g_att[NTOT_PIX];

// shapes: (8,64,256,256)(8,128,128,128)(8,256,64,64)(8,512,32,32)(8,512,16,16)
__constant__ int c_C[5]       = {64, 128, 256, 512, 512};
__constant__ int c_HW[5]      = {65536, 16384, 4096, 1024, 256};
__constant__ int c_lgHW[5]    = {16, 14, 12, 10, 8};
__constant__ int c_W[5]       = {256, 128, 64, 32, 16};
__constant__ int c_poff[5]    = {0, 524288, 655360, 688128, 696320};          // pixel offsets
__constant__ int c_eoff[5]    = {0, 33554432, 50331648, 58720256, 62914560};  // element offsets
__constant__ int c_convcum[5] = {0, 2048, 2560, 2688, 2720};   // conv blocks
__constant__ int c_tpn[5]     = {256, 64, 16, 4, 1};           // 16x16 tiles per image
__constant__ int c_tilesX[5]  = {16, 8, 4, 2, 1};

// reduce tiling: P = 512,256,128,64,32 ; nsub = 2,4,8,16,32 ;
// blocks/image = 128,64,32,16,8 -> 1024,512,256,128,64 = 1984 (heavy-C first)
__constant__ int c_rstart[5]  = {960, 448, 192, 64, 0};
__constant__ int c_lgP[5]     = {9, 8, 7, 6, 5};
__constant__ int c_lgns[5]    = {1, 2, 3, 4, 5};
__constant__ int c_lgbpi[5]   = {7, 6, 5, 4, 3};

// gate tiling: 8192 elements/block; per-tensor blocks 4096,2048,1024,512,128
__constant__ int c_gcum[5]    = {0, 4096, 6144, 7168, 7680};
__constant__ int c_lgpnb[5]   = {9, 8, 7, 6, 4};
__constant__ int c_lgnhw[5]   = {6, 4, 2, 0, 0};
__constant__ int c_lgnch[5]   = {3, 3, 3, 3, 5};
__constant__ int c_lgchunk[5] = {10, 10, 10, 10, 8};

// ---------------------------------------------------------------------------
// Phase 1: channel mean + max, contiguous-read form, __ldcs streaming reads.
// ---------------------------------------------------------------------------
__global__ __launch_bounds__(256, 4) void reduce_kernel(
    const float* __restrict__ t0, const float* __restrict__ t1,
    const float* __restrict__ t2, const float* __restrict__ t3,
    const float* __restrict__ t4)
{
    __shared__ float4 sh_s[256];
    __shared__ float4 sh_m[256];

    const int b = blockIdx.x;
    int i;
    if      (b < 64)  i = 4;
    else if (b < 192) i = 3;
    else if (b < 448) i = 2;
    else if (b < 960) i = 1;
    else              i = 0;

    const float* srcs[5] = {t0, t1, t2, t3, t4};
    const float* __restrict__ src = srcs[i];

    const int tid   = threadIdx.x;
    const int r     = b - c_rstart[i];
    const int lgP   = c_lgP[i];
    const int lgns  = c_lgns[i];
    const int lgbpi = c_lgbpi[i];
    const int nsub  = 1 << lgns;
    const int Tpx   = 256 >> lgns;

    const int n     = r >> lgbpi;
    const int chunk = r & ((1 << lgbpi) - 1);
    const int hw0   = chunk << lgP;

    const int HW = c_HW[i];
    const int C  = c_C[i];
    const int sub = tid >> (8 - lgns);
    const int pxt = tid & (Tpx - 1);

    const float4* __restrict__ p = reinterpret_cast<const float4*>(
        src + ((size_t)(n * C + sub)) * HW + hw0 + (pxt << 2));
    const size_t step4 = ((size_t)HW << lgns) >> 2;   // nsub*HW floats / 4

    float4 s = make_float4(0.f, 0.f, 0.f, 0.f);
    float4 m = make_float4(-CUDART_INF_F, -CUDART_INF_F, -CUDART_INF_F, -CUDART_INF_F);

    const int iters = C >> (lgns + 2);                // 8,8,8,8,4
    for (int it = 0; it < iters; it++) {
        float4 v0 = __ldcs(p);
        float4 v1 = __ldcs(p + step4);
        float4 v2 = __ldcs(p + 2 * step4);
        float4 v3 = __ldcs(p + 3 * step4);
        p += 4 * step4;
        s.x += v0.x + v1.x; s.y += v0.y + v1.y; s.z += v0.z + v1.z; s.w += v0.w + v1.w;
        s.x += v2.x + v3.x; s.y += v2.y + v3.y; s.z += v2.z + v3.z; s.w += v2.w + v3.w;
        m.x = fmaxf(fmaxf(m.x, v0.x), fmaxf(v1.x, fmaxf(v2.x, v3.x)));
        m.y = fmaxf(fmaxf(m.y, v0.y), fmaxf(v1.y, fmaxf(v2.y, v3.y)));
        m.z = fmaxf(fmaxf(m.z, v0.z), fmaxf(v1.z, fmaxf(v2.z, v3.z)));
        m.w = fmaxf(fmaxf(m.w, v0.w), fmaxf(v1.w, fmaxf(v2.w, v3.w)));
    }

    sh_s[tid] = s;
    sh_m[tid] = m;
    __syncthreads();
    if (tid < Tpx) {
        for (int k = 1; k < nsub; k++) {
            float4 s2 = sh_s[tid + k * Tpx];
            float4 m2 = sh_m[tid + k * Tpx];
            s.x += s2.x; s.y += s2.y; s.z += s2.z; s.w += s2.w;
            m.x = fmaxf(m.x, m2.x); m.y = fmaxf(m.y, m2.y);
            m.z = fmaxf(m.z, m2.z); m.w = fmaxf(m.w, m2.w);
        }
        const float inv = 1.0f / (float)C;
        s.x *= inv; s.y *= inv; s.z *= inv; s.w *= inv;
        const int ppix = c_poff[i] + (n << c_lgHW[i]) + hw0 + (pxt << 2);
        const int q4 = ppix >> 2;
        // avg/max are REUSED by conv -> default (L2-allocating) stores
        reinterpret_cast<float4*>(g_avg)[q4] = s;
        reinterpret_cast<float4*>(g_max)[q4] = m;
    }
}

// ---------------------------------------------------------------------------
// Phase 2: dilated 7x7 conv (dilation 3, zero pad 9) over [avg,max], + bias,
// sigmoid. Block = 16x16 output tile; SMEM holds 34x34 halo of both maps.
// Grid = 2728. lax.conv is cross-correlation (no kernel flip).
// ---------------------------------------------------------------------------
__global__ __launch_bounds__(256) void conv_kernel(
    const float* __restrict__ cw, const float* __restrict__ cb)
{
    __shared__ float s_av[34 * 34];
    __shared__ float s_mx[34 * 34];
    __shared__ float s_w[98];

    int b = blockIdx.x;
    int i = 0;
    if (b >= 2048) i = 1;
    if (b >= 2560) i = 2;
    if (b >= 2688) i = 3;
    if (b >= 2720) i = 4;

    const int r      = b - c_convcum[i];
    const int tpn    = c_tpn[i];
    const int n      = r / tpn;
    const int tl     = r - n * tpn;
    const int tilesX = c_tilesX[i];
    const int ty0    = (tl / tilesX) << 4;
    const int tx0    = (tl % tilesX) << 4;
    const int Wd     = c_W[i];
    const int po     = c_poff[i] + (n << c_lgHW[i]);

    const int tid = threadIdx.x;
    if (tid < 98) s_w[tid] = cw[tid];

    for (int idx = tid; idx < 34 * 34; idx += 256) {
        int yy = idx / 34;
        int xx = idx - yy * 34;
        int h  = ty0 + yy - 9;
        int w  = tx0 + xx - 9;
        float a = 0.0f, m = 0.0f;
        if ((unsigned)h < (unsigned)Wd && (unsigned)w < (unsigned)Wd) { // H==W
            int q = po + h * Wd + w;
            a = g_avg[q];
            m = g_max[q];
        }
        s_av[idx] = a;
        s_mx[idx] = m;
    }
    __syncthreads();

    const int ty = tid >> 4;
    const int tx = tid & 15;

    float acc = cb[0];
#pragma unroll
    for (int kh = 0; kh < 7; kh++) {
#pragma unroll
        for (int kw = 0; kw < 7; kw++) {
            int s = (ty + kh * 3) * 34 + (tx + kw * 3);
            acc = fmaf(s_av[s], s_w[kh * 7 + kw],      acc);
            acc = fmaf(s_mx[s], s_w[49 + kh * 7 + kw], acc);
        }
    }
    float att = 1.0f / (1.0f + expf(-acc));
    g_att[po + (ty0 + ty) * Wd + (tx0 + tx)] = att;   // reused by gate -> default
}

// ---------------------------------------------------------------------------
// Phase 3: out = t * (1 + att), tiled for att reuse. att staged in SMEM.
// src reads: __ldcs (single-use). out writes: __stcs (write-once stream).
// Grid = 7808, uniform work.
// ---------------------------------------------------------------------------
__global__ __launch_bounds__(256) void gate_kernel(
    const float* __restrict__ t0, const float* __restrict__ t1,
    const float* __restrict__ t2, const float* __restrict__ t3,
    const float* __restrict__ t4, float* __restrict__ out)
{
    __shared__ __align__(16) float s_att[1024];

    const int b = blockIdx.x;
    int i = 0;
    if (b >= 4096) i = 1;
    if (b >= 6144) i = 2;
    if (b >= 7168) i = 3;
    if (b >= 7680) i = 4;

    const float* srcs[5] = {t0, t1, t2, t3, t4};
    const float* __restrict__ src = srcs[i];

    const int tid     = threadIdx.x;
    const int r       = b - c_gcum[i];
    const int lgpnb   = c_lgpnb[i];
    const int lgnhw   = c_lgnhw[i];
    const int lgnch   = c_lgnch[i];
    const int lgchunk = c_lgchunk[i];
    const int lgHW    = c_lgHW[i];

    const int n      = r >> lgpnb;
    const int rem    = r & ((1 << lgpnb) - 1);
    const int cchunk = rem >> lgnhw;
    const int hwc    = rem & ((1 << lgnhw) - 1);
    const int c0     = cchunk << lgnch;
    const int hw0    = hwc << lgchunk;
    const int chunkpx = 1 << lgchunk;

    const int ebase   = ((n * c_C[i] + c0) << lgHW) + hw0;
    const int attbase = c_poff[i] + (n << lgHW) + hw0;

    if (tid < (chunkpx >> 2)) {
        // att is reused across channel chunks -> default (L2-cached) load
        reinterpret_cast<float4*>(s_att)[tid] =
            *reinterpret_cast<const float4*>(&g_att[attbase + (tid << 2)]);
    }
    __syncthreads();

    const int chunkm1 = chunkpx - 1;

    float4 v[8];
#pragma unroll
    for (int j = 0; j < 8; j++) {
        int f  = ((j << 8) + tid) << 2;
        int ch = f >> lgchunk;
        int px = f & chunkm1;
        v[j] = __ldcs(reinterpret_cast<const float4*>(&src[ebase + (ch << lgHW) + px]));
    }
    const int eoff = c_eoff[i];
#pragma unroll
    for (int j = 0; j < 8; j++) {
        int f  = ((j << 8) + tid) << 2;
        int ch = f >> lgchunk;
        int px = f & chunkm1;
        float4 a = *reinterpret_cast<const float4*>(&s_att[px]);
        float4 o;
        o.x = fmaf(v[j].x, a.x, v[j].x);
        o.y = fmaf(v[j].y, a.y, v[j].y);
        o.z = fmaf(v[j].z, a.z, v[j].z);
        o.w = fmaf(v[j].w, a.w, v[j].w);
        __stcs(reinterpret_cast<float4*>(&out[eoff + ebase + (ch << lgHW) + px]), o);
    }
}

// ---------------------------------------------------------------------------
extern "C" void kernel_launch(void* const* d_in, const int* in_sizes, int n_in,
                              void* d_out, int out_size)
{
    const float* t0 = (const float*)d_in[0];
    const float* t1 = (const float*)d_in[1];
    const float* t2 = (const float*)d_in[2];
    const float* t3 = (const float*)d_in[3];
    const float* t4 = (const float*)d_in[4];
    const float* cw = (const float*)d_in[5];
    const float* cb = (const float*)d_in[6];
    float* out = (float*)d_out;

    reduce_kernel<<<1984, 256>>>(t0, t1, t2, t3, t4);
    conv_kernel<<<2728, 256>>>(cw, cb);
    gate_kernel<<<7808, 256>>>(t0, t1, t2, t3, t4, out);
}

// round 16
// speedup vs baseline: 1.0823x; 1.0158x over previous
#include <cuda_runtime.h>
#include <math_constants.h>

// ---------------------------------------------------------------------------
// SC_Att_Bridge: 5-level spatial attention (CBAM-style), fp32.
// 3-kernel structure + streaming cache hints (R15 = 146.2us baseline).
// R16: reduce uses 8-deep LDG.128 batching at (256,3) -> ~98KB/SM in flight
// (R8/R10 showed throughput scaling ~linearly with in-flight bytes).
// ---------------------------------------------------------------------------

#define NTOT_PIX 698368   // sum over tensors of N*H*W (N=8)

__device__ float g_avg[NTOT_PIX];
__device__ float g_max[NTOT_PIX];
__device__ float g_att[NTOT_PIX];

// shapes: (8,64,256,256)(8,128,128,128)(8,256,64,64)(8,512,32,32)(8,512,16,16)
__constant__ int c_C[5]       = {64, 128, 256, 512, 512};
__constant__ int c_HW[5]      = {65536, 16384, 4096, 1024, 256};
__constant__ int c_lgHW[5]    = {16, 14, 12, 10, 8};
__constant__ int c_W[5]       = {256, 128, 64, 32, 16};
__constant__ int c_poff[5]    = {0, 524288, 655360, 688128, 696320};          // pixel offsets
__constant__ int c_eoff[5]    = {0, 33554432, 50331648, 58720256, 62914560};  // element offsets
__constant__ int c_convcum[5] = {0, 2048, 2560, 2688, 2720};   // conv blocks
__constant__ int c_tpn[5]     = {256, 64, 16, 4, 1};           // 16x16 tiles per image
__constant__ int c_tilesX[5]  = {16, 8, 4, 2, 1};

// reduce tiling: P = 512,256,128,64,32 ; nsub = 2,4,8,16,32 ;
// blocks/image = 128,64,32,16,8 -> 1024,512,256,128,64 = 1984 (heavy-C first)
__constant__ int c_rstart[5]  = {960, 448, 192, 64, 0};
__constant__ int c_lgP[5]     = {9, 8, 7, 6, 5};
__constant__ int c_lgns[5]    = {1, 2, 3, 4, 5};
__constant__ int c_lgbpi[5]   = {7, 6, 5, 4, 3};

// gate tiling: 8192 elements/block; per-tensor blocks 4096,2048,1024,512,128
__constant__ int c_gcum[5]    = {0, 4096, 6144, 7168, 7680};
__constant__ int c_lgpnb[5]   = {9, 8, 7, 6, 4};
__constant__ int c_lgnhw[5]   = {6, 4, 2, 0, 0};
__constant__ int c_lgnch[5]   = {3, 3, 3, 3, 5};
__constant__ int c_lgchunk[5] = {10, 10, 10, 10, 8};

// ---------------------------------------------------------------------------
// Phase 1: channel mean + max, contiguous-read form, __ldcs streaming reads,
// 8-deep load batch. iters = C/(8*nsub) = 4,4,4,4,2 (exact).
// ---------------------------------------------------------------------------
__global__ __launch_bounds__(256, 3) void reduce_kernel(
    const float* __restrict__ t0, const float* __restrict__ t1,
    const float* __restrict__ t2, const float* __restrict__ t3,
    const float* __restrict__ t4)
{
    __shared__ float4 sh_s[256];
    __shared__ float4 sh_m[256];

    const int b = blockIdx.x;
    int i;
    if      (b < 64)  i = 4;
    else if (b < 192) i = 3;
    else if (b < 448) i = 2;
    else if (b < 960) i = 1;
    else              i = 0;

    const float* srcs[5] = {t0, t1, t2, t3, t4};
    const float* __restrict__ src = srcs[i];

    const int tid   = threadIdx.x;
    const int r     = b - c_rstart[i];
    const int lgP   = c_lgP[i];
    const int lgns  = c_lgns[i];
    const int lgbpi = c_lgbpi[i];
    const int nsub  = 1 << lgns;
    const int Tpx   = 256 >> lgns;

    const int n     = r >> lgbpi;
    const int chunk = r & ((1 << lgbpi) - 1);
    const int hw0   = chunk << lgP;

    const int HW = c_HW[i];
    const int C  = c_C[i];
    const int sub = tid >> (8 - lgns);
    const int pxt = tid & (Tpx - 1);

    const float4* __restrict__ p = reinterpret_cast<const float4*>(
        src + ((size_t)(n * C + sub)) * HW + hw0 + (pxt << 2));
    const size_t step4 = ((size_t)HW << lgns) >> 2;   // nsub*HW floats / 4

    float4 s = make_float4(0.f, 0.f, 0.f, 0.f);
    float4 m = make_float4(-CUDART_INF_F, -CUDART_INF_F, -CUDART_INF_F, -CUDART_INF_F);

    const int iters = C >> (lgns + 3);                // C/(8*nsub): 4,4,4,4,2
    for (int it = 0; it < iters; it++) {
        float4 v[8];
#pragma unroll
        for (int k = 0; k < 8; k++)
            v[k] = __ldcs(p + (size_t)k * step4);
        p += 8 * step4;
#pragma unroll
        for (int k = 0; k < 8; k++) {
            s.x += v[k].x; s.y += v[k].y; s.z += v[k].z; s.w += v[k].w;
            m.x = fmaxf(m.x, v[k].x); m.y = fmaxf(m.y, v[k].y);
            m.z = fmaxf(m.z, v[k].z); m.w = fmaxf(m.w, v[k].w);
        }
    }

    sh_s[tid] = s;
    sh_m[tid] = m;
    __syncthreads();
    if (tid < Tpx) {
        for (int k = 1; k < nsub; k++) {
            float4 s2 = sh_s[tid + k * Tpx];
            float4 m2 = sh_m[tid + k * Tpx];
            s.x += s2.x; s.y += s2.y; s.z += s2.z; s.w += s2.w;
            m.x = fmaxf(m.x, m2.x); m.y = fmaxf(m.y, m2.y);
            m.z = fmaxf(m.z, m2.z); m.w = fmaxf(m.w, m2.w);
        }
        const float inv = 1.0f / (float)C;
        s.x *= inv; s.y *= inv; s.z *= inv; s.w *= inv;
        const int ppix = c_poff[i] + (n << c_lgHW[i]) + hw0 + (pxt << 2);
        const int q4 = ppix >> 2;
        // avg/max are REUSED by conv -> default (L2-allocating) stores
        reinterpret_cast<float4*>(g_avg)[q4] = s;
        reinterpret_cast<float4*>(g_max)[q4] = m;
    }
}

// ---------------------------------------------------------------------------
// Phase 2: dilated 7x7 conv (dilation 3, zero pad 9) over [avg,max], + bias,
// sigmoid. Block = 16x16 output tile; SMEM holds 34x34 halo of both maps.
// Grid = 2728. lax.conv is cross-correlation (no kernel flip).
// ---------------------------------------------------------------------------
__global__ __launch_bounds__(256) void conv_kernel(
    const float* __restrict__ cw, const float* __restrict__ cb)
{
    __shared__ float s_av[34 * 34];
    __shared__ float s_mx[34 * 34];
    __shared__ float s_w[98];

    int b = blockIdx.x;
    int i = 0;
    if (b >= 2048) i = 1;
    if (b >= 2560) i = 2;
    if (b >= 2688) i = 3;
    if (b >= 2720) i = 4;

    const int r      = b - c_convcum[i];
    const int tpn    = c_tpn[i];
    const int n      = r / tpn;
    const int tl     = r - n * tpn;
    const int tilesX = c_tilesX[i];
    const int ty0    = (tl / tilesX) << 4;
    const int tx0    = (tl % tilesX) << 4;
    const int Wd     = c_W[i];
    const int po     = c_poff[i] + (n << c_lgHW[i]);

    const int tid = threadIdx.x;
    if (tid < 98) s_w[tid] = cw[tid];

    for (int idx = tid; idx < 34 * 34; idx += 256) {
        int yy = idx / 34;
        int xx = idx - yy * 34;
        int h  = ty0 + yy - 9;
        int w  = tx0 + xx - 9;
        float a = 0.0f, m = 0.0f;
        if ((unsigned)h < (unsigned)Wd && (unsigned)w < (unsigned)Wd) { // H==W
            int q = po + h * Wd + w;
            a = g_avg[q];
            m = g_max[q];
        }
        s_av[idx] = a;
        s_mx[idx] = m;
    }
    __syncthreads();

    const int ty = tid >> 4;
    const int tx = tid & 15;

    float acc = cb[0];
#pragma unroll
    for (int kh = 0; kh < 7; kh++) {
#pragma unroll
        for (int kw = 0; kw < 7; kw++) {
            int s = (ty + kh * 3) * 34 + (tx + kw * 3);
            acc = fmaf(s_av[s], s_w[kh * 7 + kw],      acc);
            acc = fmaf(s_mx[s], s_w[49 + kh * 7 + kw], acc);
        }
    }
    float att = 1.0f / (1.0f + expf(-acc));
    g_att[po + (ty0 + ty) * Wd + (tx0 + tx)] = att;   // reused by gate -> default
}

// ---------------------------------------------------------------------------
// Phase 3: out = t * (1 + att), tiled for att reuse. att staged in SMEM.
// src reads: __ldcs (single-use). out writes: __stcs (write-once stream).
// Grid = 7808, uniform work.
// ---------------------------------------------------------------------------
__global__ __launch_bounds__(256) void gate_kernel(
    const float* __restrict__ t0, const float* __restrict__ t1,
    const float* __restrict__ t2, const float* __restrict__ t3,
    const float* __restrict__ t4, float* __restrict__ out)
{
    __shared__ __align__(16) float s_att[1024];

    const int b = blockIdx.x;
    int i = 0;
    if (b >= 4096) i = 1;
    if (b >= 6144) i = 2;
    if (b >= 7168) i = 3;
    if (b >= 7680) i = 4;

    const float* srcs[5] = {t0, t1, t2, t3, t4};
    const float* __restrict__ src = srcs[i];

    const int tid     = threadIdx.x;
    const int r       = b - c_gcum[i];
    const int lgpnb   = c_lgpnb[i];
    const int lgnhw   = c_lgnhw[i];
    const int lgnch   = c_lgnch[i];
    const int lgchunk = c_lgchunk[i];
    const int lgHW    = c_lgHW[i];

    const int n      = r >> lgpnb;
    const int rem    = r & ((1 << lgpnb) - 1);
    const int cchunk = rem >> lgnhw;
    const int hwc    = rem & ((1 << lgnhw) - 1);
    const int c0     = cchunk << lgnch;
    const int hw0    = hwc << lgchunk;
    const int chunkpx = 1 << lgchunk;

    const int ebase   = ((n * c_C[i] + c0) << lgHW) + hw0;
    const int attbase = c_poff[i] + (n << lgHW) + hw0;

    if (tid < (chunkpx >> 2)) {
        // att is reused across channel chunks -> default (L2-cached) load
        reinterpret_cast<float4*>(s_att)[tid] =
            *reinterpret_cast<const float4*>(&g_att[attbase + (tid << 2)]);
    }
    __syncthreads();

    const int chunkm1 = chunkpx - 1;

    float4 v[8];
#pragma unroll
    for (int j = 0; j < 8; j++) {
        int f  = ((j << 8) + tid) << 2;
        int ch = f >> lgchunk;
        int px = f & chunkm1;
        v[j] = __ldcs(reinterpret_cast<const float4*>(&src[ebase + (ch << lgHW) + px]));
    }
    const int eoff = c_eoff[i];
#pragma unroll
    for (int j = 0; j < 8; j++) {
        int f  = ((j << 8) + tid) << 2;
        int ch = f >> lgchunk;
        int px = f & chunkm1;
        float4 a = *reinterpret_cast<const float4*>(&s_att[px]);
        float4 o;
        o.x = fmaf(v[j].x, a.x, v[j].x);
        o.y = fmaf(v[j].y, a.y, v[j].y);
        o.z = fmaf(v[j].z, a.z, v[j].z);
        o.w = fmaf(v[j].w, a.w, v[j].w);
        __stcs(reinterpret_cast<float4*>(&out[eoff + ebase + (ch << lgHW) + px]), o);
    }
}

// ---------------------------------------------------------------------------
extern "C" void kernel_launch(void* const* d_in, const int* in_sizes, int n_in,
                              void* d_out, int out_size)
{
    const float* t0 = (const float*)d_in[0];
    const float* t1 = (const float*)d_in[1];
    const float* t2 = (const float*)d_in[2];
    const float* t3 = (const float*)d_in[3];
    const float* t4 = (const float*)d_in[4];
    const float* cw = (const float*)d_in[5];
    const float* cb = (const float*)d_in[6];
    float* out = (float*)d_out;

    reduce_kernel<<<1984, 256>>>(t0, t1, t2, t3, t4);
    conv_kernel<<<2728, 256>>>(cw, cb);
    gate_kernel<<<7808, 256>>>(t0, t1, t2, t3, t4, out);
}

// round 17
// speedup vs baseline: 1.0927x; 1.0097x over previous
#include <cuda_runtime.h>
#include <math_constants.h>

// ---------------------------------------------------------------------------
// SC_Att_Bridge: 5-level spatial attention (CBAM-style), fp32.
// 3-kernel structure + streaming cache hints (R16 = 143.9us baseline).
// R17: reduce uses 16-deep LDG.128 batching at (256,2) -> ~131KB/SM in
// flight, next step on the measured in-flight-bytes -> bandwidth curve
// (49KB:5.03, 65KB:5.44, 98KB:5.87 TB/s).
// ---------------------------------------------------------------------------

#define NTOT_PIX 698368   // sum over tensors of N*H*W (N=8)

__device__ float g_avg[NTOT_PIX];
__device__ float g_max[NTOT_PIX];
__device__ float g_att[NTOT_PIX];

// shapes: (8,64,256,256)(8,128,128,128)(8,256,64,64)(8,512,32,32)(8,512,16,16)
__constant__ int c_C[5]       = {64, 128, 256, 512, 512};
__constant__ int c_HW[5]      = {65536, 16384, 4096, 1024, 256};
__constant__ int c_lgHW[5]    = {16, 14, 12, 10, 8};
__constant__ int c_W[5]       = {256, 128, 64, 32, 16};
__constant__ int c_poff[5]    = {0, 524288, 655360, 688128, 696320};          // pixel offsets
__constant__ int c_eoff[5]    = {0, 33554432, 50331648, 58720256, 62914560};  // element offsets
__constant__ int c_convcum[5] = {0, 2048, 2560, 2688, 2720};   // conv blocks
__constant__ int c_tpn[5]     = {256, 64, 16, 4, 1};           // 16x16 tiles per image
__constant__ int c_tilesX[5]  = {16, 8, 4, 2, 1};

// reduce tiling: P = 512,256,128,64,32 ; nsub = 2,4,8,16,32 ;
// blocks/image = 128,64,32,16,8 -> 1024,512,256,128,64 = 1984 (heavy-C first)
__constant__ int c_rstart[5]  = {960, 448, 192, 64, 0};
__constant__ int c_lgP[5]     = {9, 8, 7, 6, 5};
__constant__ int c_lgns[5]    = {1, 2, 3, 4, 5};
__constant__ int c_lgbpi[5]   = {7, 6, 5, 4, 3};

// gate tiling: 8192 elements/block; per-tensor blocks 4096,2048,1024,512,128
__constant__ int c_gcum[5]    = {0, 4096, 6144, 7168, 7680};
__constant__ int c_lgpnb[5]   = {9, 8, 7, 6, 4};
__constant__ int c_lgnhw[5]   = {6, 4, 2, 0, 0};
__constant__ int c_lgnch[5]   = {3, 3, 3, 3, 5};
__constant__ int c_lgchunk[5] = {10, 10, 10, 10, 8};

// ---------------------------------------------------------------------------
// Phase 1: channel mean + max, contiguous-read form, __ldcs streaming reads,
// 16-deep load batch. iters = C/(16*nsub) = 2,2,2,2,1 (exact).
// ---------------------------------------------------------------------------
__global__ __launch_bounds__(256, 2) void reduce_kernel(
    const float* __restrict__ t0, const float* __restrict__ t1,
    const float* __restrict__ t2, const float* __restrict__ t3,
    const float* __restrict__ t4)
{
    __shared__ float4 sh_s[256];
    __shared__ float4 sh_m[256];

    const int b = blockIdx.x;
    int i;
    if      (b < 64)  i = 4;
    else if (b < 192) i = 3;
    else if (b < 448) i = 2;
    else if (b < 960) i = 1;
    else              i = 0;

    const float* srcs[5] = {t0, t1, t2, t3, t4};
    const float* __restrict__ src = srcs[i];

    const int tid   = threadIdx.x;
    const int r     = b - c_rstart[i];
    const int lgP   = c_lgP[i];
    const int lgns  = c_lgns[i];
    const int lgbpi = c_lgbpi[i];
    const int nsub  = 1 << lgns;
    const int Tpx   = 256 >> lgns;

    const int n     = r >> lgbpi;
    const int chunk = r & ((1 << lgbpi) - 1);
    const int hw0   = chunk << lgP;

    const int HW = c_HW[i];
    const int C  = c_C[i];
    const int sub = tid >> (8 - lgns);
    const int pxt = tid & (Tpx - 1);

    const float4* __restrict__ p = reinterpret_cast<const float4*>(
        src + ((size_t)(n * C + sub)) * HW + hw0 + (pxt << 2));
    const size_t step4 = ((size_t)HW << lgns) >> 2;   // nsub*HW floats / 4

    float4 s = make_float4(0.f, 0.f, 0.f, 0.f);
    float4 m = make_float4(-CUDART_INF_F, -CUDART_INF_F, -CUDART_INF_F, -CUDART_INF_F);

    const int iters = C >> (lgns + 4);                // C/(16*nsub): 2,2,2,2,1
    for (int it = 0; it < iters; it++) {
        float4 v[16];
#pragma unroll
        for (int k = 0; k < 16; k++)
            v[k] = __ldcs(p + (size_t)k * step4);
        p += 16 * step4;
#pragma unroll
        for (int k = 0; k < 16; k++) {
            s.x += v[k].x; s.y += v[k].y; s.z += v[k].z; s.w += v[k].w;
            m.x = fmaxf(m.x, v[k].x); m.y = fmaxf(m.y, v[k].y);
            m.z = fmaxf(m.z, v[k].z); m.w = fmaxf(m.w, v[k].w);
        }
    }

    sh_s[tid] = s;
    sh_m[tid] = m;
    __syncthreads();
    if (tid < Tpx) {
        for (int k = 1; k < nsub; k++) {
            float4 s2 = sh_s[tid + k * Tpx];
            float4 m2 = sh_m[tid + k * Tpx];
            s.x += s2.x; s.y += s2.y; s.z += s2.z; s.w += s2.w;
            m.x = fmaxf(m.x, m2.x); m.y = fmaxf(m.y, m2.y);
            m.z = fmaxf(m.z, m2.z); m.w = fmaxf(m.w, m2.w);
        }
        const float inv = 1.0f / (float)C;
        s.x *= inv; s.y *= inv; s.z *= inv; s.w *= inv;
        const int ppix = c_poff[i] + (n << c_lgHW[i]) + hw0 + (pxt << 2);
        const int q4 = ppix >> 2;
        // avg/max are REUSED by conv -> default (L2-allocating) stores
        reinterpret_cast<float4*>(g_avg)[q4] = s;
        reinterpret_cast<float4*>(g_max)[q4] = m;
    }
}

// ---------------------------------------------------------------------------
// Phase 2: dilated 7x7 conv (dilation 3, zero pad 9) over [avg,max], + bias,
// sigmoid. Block = 16x16 output tile; SMEM holds 34x34 halo of both maps.
// Grid = 2728. lax.conv is cross-correlation (no kernel flip).
// ---------------------------------------------------------------------------
__global__ __launch_bounds__(256) void conv_kernel(
    const float* __restrict__ cw, const float* __restrict__ cb)
{
    __shared__ float s_av[34 * 34];
    __shared__ float s_mx[34 * 34];
    __shared__ float s_w[98];

    int b = blockIdx.x;
    int i = 0;
    if (b >= 2048) i = 1;
    if (b >= 2560) i = 2;
    if (b >= 2688) i = 3;
    if (b >= 2720) i = 4;

    const int r      = b - c_convcum[i];
    const int tpn    = c_tpn[i];
    const int n      = r / tpn;
    const int tl     = r - n * tpn;
    const int tilesX = c_tilesX[i];
    const int ty0    = (tl / tilesX) << 4;
    const int tx0    = (tl % tilesX) << 4;
    const int Wd     = c_W[i];
    const int po     = c_poff[i] + (n << c_lgHW[i]);

    const int tid = threadIdx.x;
    if (tid < 98) s_w[tid] = cw[tid];

    for (int idx = tid; idx < 34 * 34; idx += 256) {
        int yy = idx / 34;
        int xx = idx - yy * 34;
        int h  = ty0 + yy - 9;
        int w  = tx0 + xx - 9;
        float a = 0.0f, m = 0.0f;
        if ((unsigned)h < (unsigned)Wd && (unsigned)w < (unsigned)Wd) { // H==W
            int q = po + h * Wd + w;
            a = g_avg[q];
            m = g_max[q];
        }
        s_av[idx] = a;
        s_mx[idx] = m;
    }
    __syncthreads();

    const int ty = tid >> 4;
    const int tx = tid & 15;

    float acc = cb[0];
#pragma unroll
    for (int kh = 0; kh < 7; kh++) {
#pragma unroll
        for (int kw = 0; kw < 7; kw++) {
            int s = (ty + kh * 3) * 34 + (tx + kw * 3);
            acc = fmaf(s_av[s], s_w[kh * 7 + kw],      acc);
            acc = fmaf(s_mx[s], s_w[49 + kh * 7 + kw], acc);
        }
    }
    float att = 1.0f / (1.0f + expf(-acc));
    g_att[po + (ty0 + ty) * Wd + (tx0 + tx)] = att;   // reused by gate -> default
}

// ---------------------------------------------------------------------------
// Phase 3: out = t * (1 + att), tiled for att reuse. att staged in SMEM.
// src reads: __ldcs (single-use). out writes: __stcs (write-once stream).
// Grid = 7808, uniform work.
// ---------------------------------------------------------------------------
__global__ __launch_bounds__(256) void gate_kernel(
    const float* __restrict__ t0, const float* __restrict__ t1,
    const float* __restrict__ t2, const float* __restrict__ t3,
    const float* __restrict__ t4, float* __restrict__ out)
{
    __shared__ __align__(16) float s_att[1024];

    const int b = blockIdx.x;
    int i = 0;
    if (b >= 4096) i = 1;
    if (b >= 6144) i = 2;
    if (b >= 7168) i = 3;
    if (b >= 7680) i = 4;

    const float* srcs[5] = {t0, t1, t2, t3, t4};
    const float* __restrict__ src = srcs[i];

    const int tid     = threadIdx.x;
    const int r       = b - c_gcum[i];
    const int lgpnb   = c_lgpnb[i];
    const int lgnhw   = c_lgnhw[i];
    const int lgnch   = c_lgnch[i];
    const int lgchunk = c_lgchunk[i];
    const int lgHW    = c_lgHW[i];

    const int n      = r >> lgpnb;
    const int rem    = r & ((1 << lgpnb) - 1);
    const int cchunk = rem >> lgnhw;
    const int hwc    = rem & ((1 << lgnhw) - 1);
    const int c0     = cchunk << lgnch;
    const int hw0    = hwc << lgchunk;
    const int chunkpx = 1 << lgchunk;

    const int ebase   = ((n * c_C[i] + c0) << lgHW) + hw0;
    const int attbase = c_poff[i] + (n << lgHW) + hw0;

    if (tid < (chunkpx >> 2)) {
        // att is reused across channel chunks -> default (L2-cached) load
        reinterpret_cast<float4*>(s_att)[tid] =
            *reinterpret_cast<const float4*>(&g_att[attbase + (tid << 2)]);
    }
    __syncthreads();

    const int chunkm1 = chunkpx - 1;

    float4 v[8];
#pragma unroll
    for (int j = 0; j < 8; j++) {
        int f  = ((j << 8) + tid) << 2;
        int ch = f >> lgchunk;
        int px = f & chunkm1;
        v[j] = __ldcs(reinterpret_cast<const float4*>(&src[ebase + (ch << lgHW) + px]));
    }
    const int eoff = c_eoff[i];
#pragma unroll
    for (int j = 0; j < 8; j++) {
        int f  = ((j << 8) + tid) << 2;
        int ch = f >> lgchunk;
        int px = f & chunkm1;
        float4 a = *reinterpret_cast<const float4*>(&s_att[px]);
        float4 o;
        o.x = fmaf(v[j].x, a.x, v[j].x);
        o.y = fmaf(v[j].y, a.y, v[j].y);
        o.z = fmaf(v[j].z, a.z, v[j].z);
        o.w = fmaf(v[j].w, a.w, v[j].w);
        __stcs(reinterpret_cast<float4*>(&out[eoff + ebase + (ch << lgHW) + px]), o);
    }
}

// ---------------------------------------------------------------------------
extern "C" void kernel_launch(void* const* d_in, const int* in_sizes, int n_in,
                              void* d_out, int out_size)
{
    const float* t0 = (const float*)d_in[0];
    const float* t1 = (const float*)d_in[1];
    const float* t2 = (const float*)d_in[2];
    const float* t3 = (const float*)d_in[3];
    const float* t4 = (const float*)d_in[4];
    const float* cw = (const float*)d_in[5];
    const float* cb = (const float*)d_in[6];
    float* out = (float*)d_out;

    reduce_kernel<<<1984, 256>>>(t0, t1, t2, t3, t4);
    conv_kernel<<<2728, 256>>>(cw, cb);
    gate_kernel<<<7808, 256>>>(t0, t1, t2, t3, t4, out);
}